// round 1
// baseline (speedup 1.0000x reference)
#include <cuda_runtime.h>
#include <math.h>

#define BB 4096
#define DD 512
#define QQ 16384
#define UU 256
#define OIM_SCALE 30.0f

// ---------------- scratch (device globals; no allocation allowed) ----------
__device__ float g_inputs_n[BB * DD];          // 8 MB
__device__ float g_cls_sum[UU * DD];           // 0.5 MB
__device__ int   g_cls_cnt[UU];
__device__ int   g_unrank[UU];                 // u-th sorted unique class value
__device__ float g_uniq_emb_n[UU * DD];        // indexed by class VALUE
__device__ float g_emb_eff[(size_t)QQ * DD];   // 32 MB effective queue
__device__ unsigned char g_good[QQ];
__device__ float g_target[BB];
__device__ float g_rowsum[BB];

// ---------------- 0: zero accumulators (every launch: graph replays!) ------
__global__ void k_init() {
    int stride = gridDim.x * blockDim.x;
    int i = blockIdx.x * blockDim.x + threadIdx.x;
    for (int idx = i; idx < UU * DD; idx += stride) g_cls_sum[idx] = 0.0f;
    for (int idx = i; idx < BB;      idx += stride) g_rowsum[idx]  = 0.0f;
    for (int idx = i; idx < UU;      idx += stride) g_cls_cnt[idx] = 0;
}

// ---------------- 1: normalize rows + scatter class sums -------------------
__global__ void k_row(const float* __restrict__ inputs,
                      const int*   __restrict__ labels) {
    int b = blockIdx.x;           // 4096 blocks
    int t = threadIdx.x;          // 128 threads
    const float4 v = reinterpret_cast<const float4*>(inputs + (size_t)b * DD)[t];
    float ss = v.x * v.x + v.y * v.y + v.z * v.z + v.w * v.w;
    #pragma unroll
    for (int o = 16; o; o >>= 1) ss += __shfl_xor_sync(0xffffffffu, ss, o);
    __shared__ float sh[4];
    if ((t & 31) == 0) sh[t >> 5] = ss;
    __syncthreads();
    float total = sh[0] + sh[1] + sh[2] + sh[3];
    float inv = 1.0f / fmaxf(sqrtf(total), 1e-12f);
    float4 vn = make_float4(v.x * inv, v.y * inv, v.z * inv, v.w * inv);
    reinterpret_cast<float4*>(g_inputs_n + (size_t)b * DD)[t] = vn;

    int lab = labels[b];
    float* cs = g_cls_sum + lab * DD + t * 4;
    atomicAdd(cs + 0, v.x);
    atomicAdd(cs + 1, v.y);
    atomicAdd(cs + 2, v.z);
    atomicAdd(cs + 3, v.w);
    if (t == 0) atomicAdd(&g_cls_cnt[lab], 1);
}

// ---------------- 2: class means, normalized --------------------------------
__global__ void k_class() {
    int u = blockIdx.x;           // 256 blocks
    int t = threadIdx.x;          // 128 threads
    int cnt = g_cls_cnt[u];
    float invc = cnt > 0 ? 1.0f / (float)cnt : 0.0f;
    float4 v = reinterpret_cast<const float4*>(g_cls_sum + u * DD)[t];
    v.x *= invc; v.y *= invc; v.z *= invc; v.w *= invc;
    float ss = v.x * v.x + v.y * v.y + v.z * v.z + v.w * v.w;
    #pragma unroll
    for (int o = 16; o; o >>= 1) ss += __shfl_xor_sync(0xffffffffu, ss, o);
    __shared__ float sh[4];
    if ((t & 31) == 0) sh[t >> 5] = ss;
    __syncthreads();
    float total = sh[0] + sh[1] + sh[2] + sh[3];
    float inv = 1.0f / fmaxf(sqrtf(total), 1e-12f);
    float4 vn = make_float4(v.x * inv, v.y * inv, v.z * inv, v.w * inv);
    reinterpret_cast<float4*>(g_uniq_emb_n + u * DD)[t] = vn;
}

// ---------------- 3: sorted-unique rank table -------------------------------
__global__ void k_rank() {
    int v = threadIdx.x;          // 256 threads, 1 block
    if (g_cls_cnt[v] > 0) {
        int r = 0;
        for (int w = 0; w < v; w++) r += (g_cls_cnt[w] > 0) ? 1 : 0;
        g_unrank[r] = v;
    }
}

// ---------------- 4: analytic queue resolution ------------------------------
// Slot q in the write window [h0, h0+U) ends valid with the u-th sorted unique
// class embedding. Any other slot is invalidated iff its (unique) label is in
// the batch's unique set (or was already IGNORE).
__global__ void k_build(const float* __restrict__ emb_cq,
                        const int*   __restrict__ label_cq,
                        const int*   __restrict__ header) {
    int q = blockIdx.x;           // 16384 blocks
    int t = threadIdx.x;          // 128 threads
    int h0 = header[0];
    int u = q - h0;
    u = ((u % QQ) + QQ) % QQ;
    const float* src;
    unsigned char good;
    if (u < UU) {
        int val = g_unrank[u];
        src = g_uniq_emb_n + val * DD;
        good = 1;
    } else {
        int lab = label_cq[q];
        bool inuniq = (lab >= 0 && lab < UU && g_cls_cnt[lab] > 0);
        good = (lab != -1 && !inuniq) ? 1 : 0;
        src = emb_cq + (size_t)q * DD;
    }
    reinterpret_cast<float4*>(g_emb_eff + (size_t)q * DD)[t] =
        reinterpret_cast<const float4*>(src)[t];
    if (t == 0) g_good[q] = good;
}

// ---------------- 5: target logits ------------------------------------------
__global__ void k_target(const int* __restrict__ labels) {
    int b = blockIdx.x;           // 4096 blocks
    int t = threadIdx.x;          // 128 threads
    int lab = labels[b];
    float4 a = reinterpret_cast<const float4*>(g_inputs_n + (size_t)b * DD)[t];
    float4 e = reinterpret_cast<const float4*>(g_uniq_emb_n + lab * DD)[t];
    float s = a.x * e.x + a.y * e.y + a.z * e.z + a.w * e.w;
    #pragma unroll
    for (int o = 16; o; o >>= 1) s += __shfl_xor_sync(0xffffffffu, s, o);
    __shared__ float sh[4];
    if ((t & 31) == 0) sh[t >> 5] = s;
    __syncthreads();
    if (t == 0) g_target[b] = OIM_SCALE * (sh[0] + sh[1] + sh[2] + sh[3]);
}

// ---------------- 6: fused GEMM + masked exp-sum (fixed max = SCALE) --------
// 128x128 block tile, BK=8, 256 threads, 8x8 per thread.
__global__ void __launch_bounds__(256, 2) k_gemm() {
    const int n0 = blockIdx.x * 128;
    const int m0 = blockIdx.y * 128;
    __shared__ __align__(16) float As[8][132];
    __shared__ __align__(16) float Bs[8][132];

    const int tid = threadIdx.x;
    const int tx = tid & 15;
    const int ty = tid >> 4;
    const int lrow = tid >> 1;
    const int lk = (tid & 1) * 4;

    float acc[8][8];
    #pragma unroll
    for (int i = 0; i < 8; i++)
        #pragma unroll
        for (int j = 0; j < 8; j++) acc[i][j] = 0.0f;

    const float* Ag = g_inputs_n + (size_t)(m0 + lrow) * DD + lk;
    const float* Bg = g_emb_eff  + (size_t)(n0 + lrow) * DD + lk;

    for (int k0 = 0; k0 < DD; k0 += 8) {
        float4 av = *reinterpret_cast<const float4*>(Ag + k0);
        float4 bv = *reinterpret_cast<const float4*>(Bg + k0);
        __syncthreads();
        As[lk + 0][lrow] = av.x; As[lk + 1][lrow] = av.y;
        As[lk + 2][lrow] = av.z; As[lk + 3][lrow] = av.w;
        Bs[lk + 0][lrow] = bv.x; Bs[lk + 1][lrow] = bv.y;
        Bs[lk + 2][lrow] = bv.z; Bs[lk + 3][lrow] = bv.w;
        __syncthreads();
        #pragma unroll
        for (int kk = 0; kk < 8; kk++) {
            float a[8], b[8];
            *reinterpret_cast<float4*>(&a[0]) = *reinterpret_cast<const float4*>(&As[kk][ty * 4]);
            *reinterpret_cast<float4*>(&a[4]) = *reinterpret_cast<const float4*>(&As[kk][64 + ty * 4]);
            *reinterpret_cast<float4*>(&b[0]) = *reinterpret_cast<const float4*>(&Bs[kk][tx * 4]);
            *reinterpret_cast<float4*>(&b[4]) = *reinterpret_cast<const float4*>(&Bs[kk][64 + tx * 4]);
            #pragma unroll
            for (int i = 0; i < 8; i++)
                #pragma unroll
                for (int j = 0; j < 8; j++)
                    acc[i][j] += a[i] * b[j];
        }
    }

    // epilogue: logit = SCALE*acc; accumulate exp(logit - SCALE) over good cols
    float gd[8];
    #pragma unroll
    for (int j = 0; j < 8; j++) {
        int n = n0 + ((j < 4) ? tx * 4 + j : 64 + tx * 4 + (j - 4));
        gd[j] = (float)g_good[n];
    }
    #pragma unroll
    for (int i = 0; i < 8; i++) {
        int m = m0 + ((i < 4) ? ty * 4 + i : 64 + ty * 4 + (i - 4));
        float p = 0.0f;
        #pragma unroll
        for (int j = 0; j < 8; j++)
            p += gd[j] * __expf(OIM_SCALE * acc[i][j] - OIM_SCALE);
        #pragma unroll
        for (int o = 8; o; o >>= 1) p += __shfl_xor_sync(0xffffffffu, p, o);
        if (tx == 0) atomicAdd(&g_rowsum[m], p);
    }
}

// ---------------- 7: final reduce -------------------------------------------
__global__ void k_final(float* __restrict__ out) {
    int t = threadIdx.x;          // 1024 threads, 1 block
    float s = 0.0f;
    for (int b = t; b < BB; b += 1024)
        s += (OIM_SCALE + logf(g_rowsum[b])) - g_target[b];
    #pragma unroll
    for (int o = 16; o; o >>= 1) s += __shfl_xor_sync(0xffffffffu, s, o);
    __shared__ float sh[32];
    if ((t & 31) == 0) sh[t >> 5] = s;
    __syncthreads();
    if (t == 0) {
        float tot = 0.0f;
        #pragma unroll
        for (int w = 0; w < 32; w++) tot += sh[w];
        out[0] = tot / (float)BB;
    }
}

// ---------------- launch -----------------------------------------------------
extern "C" void kernel_launch(void* const* d_in, const int* in_sizes, int n_in,
                              void* d_out, int out_size) {
    const float* inputs   = (const float*)d_in[0];   // [B,D]
    const int*   labels   = (const int*)  d_in[1];   // [B]
    const float* emb_cq   = (const float*)d_in[2];   // [Q,D]
    const int*   label_cq = (const int*)  d_in[3];   // [Q]
    // d_in[4] = age_cq (unused by the loss)
    const int*   header   = (const int*)  d_in[5];   // scalar
    float* out = (float*)d_out;

    k_init<<<256, 256>>>();
    k_row<<<BB, 128>>>(inputs, labels);
    k_class<<<UU, 128>>>();
    k_rank<<<1, UU>>>();
    k_build<<<QQ, 128>>>(emb_cq, label_cq, header);
    k_target<<<BB, 128>>>(labels);
    dim3 grid(QQ / 128, BB / 128);
    k_gemm<<<grid, 256>>>();
    k_final<<<1, 1024>>>(out);
}

// round 3
// speedup vs baseline: 7.1722x; 7.1722x over previous
#include <cuda_runtime.h>
#include <cuda_bf16.h>
#include <math.h>
#include <stdint.h>

#define BB 4096
#define DD 512
#define QQ 16384
#define UU 256
#define OIM_SCALE 30.0f

// ---------------- scratch (device globals; no allocation allowed) ----------
__device__ float g_inputs_n[BB * DD];             // fp32 normalized inputs
__device__ float g_cls_sum[UU * DD];
__device__ int   g_cls_cnt[UU];
__device__ int   g_unrank[UU];
__device__ float g_uniq_emb_n[UU * DD];
__device__ __nv_bfloat16 g_Abf[BB * DD];          // 4 MB
__device__ __nv_bfloat16 g_Bbf[(size_t)QQ * DD];  // 16 MB
__device__ unsigned char g_good[QQ];
__device__ float g_target[BB];
__device__ float g_rowsum[BB];

// ---------------- helpers ----------------------------------------------------
__device__ __forceinline__ uint32_t smem_u32(const void* p) {
    uint32_t a;
    asm("{ .reg .u64 t; cvta.to.shared.u64 t, %1; cvt.u32.u64 %0, t; }"
        : "=r"(a) : "l"(p));
    return a;
}
__device__ __forceinline__ void cpa16(uint32_t sm, const void* g) {
    asm volatile("cp.async.cg.shared.global [%0], [%1], 16;" :: "r"(sm), "l"(g));
}
__device__ __forceinline__ void cpa_commit() {
    asm volatile("cp.async.commit_group;" ::: "memory");
}
__device__ __forceinline__ void ldsm4(uint32_t* r, uint32_t addr) {
    asm volatile("ldmatrix.sync.aligned.m8n8.x4.shared.b16 {%0,%1,%2,%3}, [%4];"
                 : "=r"(r[0]), "=r"(r[1]), "=r"(r[2]), "=r"(r[3]) : "r"(addr));
}
__device__ __forceinline__ void mma16816(float* d, const uint32_t* a,
                                         const uint32_t* b) {
    asm volatile(
        "mma.sync.aligned.m16n8k16.row.col.f32.bf16.bf16.f32 "
        "{%0,%1,%2,%3}, {%4,%5,%6,%7}, {%8,%9}, {%0,%1,%2,%3};"
        : "+f"(d[0]), "+f"(d[1]), "+f"(d[2]), "+f"(d[3])
        : "r"(a[0]), "r"(a[1]), "r"(a[2]), "r"(a[3]), "r"(b[0]), "r"(b[1]));
}
#define SWZ(o) ((o) ^ (((o) >> 3) & 0x70))

__device__ __forceinline__ void pack_bf16_store(float4 v, __nv_bfloat16* dst,
                                                size_t e) {
    __nv_bfloat162 h01 = __floats2bfloat162_rn(v.x, v.y);
    __nv_bfloat162 h23 = __floats2bfloat162_rn(v.z, v.w);
    uint2 u;
    u.x = *reinterpret_cast<uint32_t*>(&h01);
    u.y = *reinterpret_cast<uint32_t*>(&h23);
    reinterpret_cast<uint2*>(dst)[e >> 2] = u;
}

// ---------------- 0: zero accumulators --------------------------------------
__global__ void k_init() {
    int stride = gridDim.x * blockDim.x;
    int i = blockIdx.x * blockDim.x + threadIdx.x;
    for (int idx = i; idx < UU * DD; idx += stride) g_cls_sum[idx] = 0.0f;
    for (int idx = i; idx < BB;      idx += stride) g_rowsum[idx]  = 0.0f;
    for (int idx = i; idx < UU;      idx += stride) g_cls_cnt[idx] = 0;
}

// ---------------- 1: normalize rows + scatter + bf16 ------------------------
__global__ void k_row(const float* __restrict__ inputs,
                      const int*   __restrict__ labels) {
    int b = blockIdx.x;
    int t = threadIdx.x;          // 128
    const float4 v = reinterpret_cast<const float4*>(inputs + (size_t)b * DD)[t];
    float ss = v.x * v.x + v.y * v.y + v.z * v.z + v.w * v.w;
    #pragma unroll
    for (int o = 16; o; o >>= 1) ss += __shfl_xor_sync(0xffffffffu, ss, o);
    __shared__ float sh[4];
    if ((t & 31) == 0) sh[t >> 5] = ss;
    __syncthreads();
    float inv = 1.0f / fmaxf(sqrtf(sh[0] + sh[1] + sh[2] + sh[3]), 1e-12f);
    float4 vn = make_float4(v.x * inv, v.y * inv, v.z * inv, v.w * inv);
    reinterpret_cast<float4*>(g_inputs_n + (size_t)b * DD)[t] = vn;
    pack_bf16_store(vn, g_Abf, (size_t)b * DD + t * 4);

    int lab = labels[b];
    float* cs = g_cls_sum + lab * DD + t * 4;
    atomicAdd(cs + 0, v.x);
    atomicAdd(cs + 1, v.y);
    atomicAdd(cs + 2, v.z);
    atomicAdd(cs + 3, v.w);
    if (t == 0) atomicAdd(&g_cls_cnt[lab], 1);
}

// ---------------- 2: class means, normalized ---------------------------------
__global__ void k_class() {
    int u = blockIdx.x;
    int t = threadIdx.x;          // 128
    int cnt = g_cls_cnt[u];
    float invc = cnt > 0 ? 1.0f / (float)cnt : 0.0f;
    float4 v = reinterpret_cast<const float4*>(g_cls_sum + u * DD)[t];
    v.x *= invc; v.y *= invc; v.z *= invc; v.w *= invc;
    float ss = v.x * v.x + v.y * v.y + v.z * v.z + v.w * v.w;
    #pragma unroll
    for (int o = 16; o; o >>= 1) ss += __shfl_xor_sync(0xffffffffu, ss, o);
    __shared__ float sh[4];
    if ((t & 31) == 0) sh[t >> 5] = ss;
    __syncthreads();
    float inv = 1.0f / fmaxf(sqrtf(sh[0] + sh[1] + sh[2] + sh[3]), 1e-12f);
    float4 vn = make_float4(v.x * inv, v.y * inv, v.z * inv, v.w * inv);
    reinterpret_cast<float4*>(g_uniq_emb_n + u * DD)[t] = vn;
}

// ---------------- 3: sorted-unique rank table --------------------------------
__global__ void k_rank() {
    int v = threadIdx.x;
    if (g_cls_cnt[v] > 0) {
        int r = 0;
        for (int w = 0; w < v; w++) r += (g_cls_cnt[w] > 0) ? 1 : 0;
        g_unrank[r] = v;
    }
}

// ---------------- 4: analytic queue resolution -> bf16 ----------------------
__global__ void k_build(const float* __restrict__ emb_cq,
                        const int*   __restrict__ label_cq,
                        const int*   __restrict__ header) {
    int q = blockIdx.x;           // 16384 blocks
    int t = threadIdx.x;          // 128
    int h0 = header[0];
    int u = q - h0;
    u = ((u % QQ) + QQ) % QQ;
    const float* src;
    unsigned char good;
    if (u < UU) {
        int val = g_unrank[u];
        src = g_uniq_emb_n + val * DD;
        good = 1;
    } else {
        int lab = label_cq[q];
        bool inuniq = (lab >= 0 && lab < UU && g_cls_cnt[lab] > 0);
        good = (lab != -1 && !inuniq) ? 1 : 0;
        src = emb_cq + (size_t)q * DD;
    }
    float4 v = reinterpret_cast<const float4*>(src)[t];
    pack_bf16_store(v, g_Bbf, (size_t)q * DD + t * 4);
    if (t == 0) g_good[q] = good;
}

// ---------------- 5: target logits (fp32 exact) ------------------------------
__global__ void k_target(const int* __restrict__ labels) {
    int b = blockIdx.x;
    int t = threadIdx.x;          // 128
    int lab = labels[b];
    float4 a = reinterpret_cast<const float4*>(g_inputs_n + (size_t)b * DD)[t];
    float4 e = reinterpret_cast<const float4*>(g_uniq_emb_n + lab * DD)[t];
    float s = a.x * e.x + a.y * e.y + a.z * e.z + a.w * e.w;
    #pragma unroll
    for (int o = 16; o; o >>= 1) s += __shfl_xor_sync(0xffffffffu, s, o);
    __shared__ float sh[4];
    if ((t & 31) == 0) sh[t >> 5] = s;
    __syncthreads();
    if (t == 0) g_target[b] = OIM_SCALE * (sh[0] + sh[1] + sh[2] + sh[3]);
}

// ---------------- 6: HMMA GEMM + fused masked exp row-sum --------------------
// CTA tile 128(M) x 128(N), K-stage 64, 3 cp.async stages, 8 warps (4m x 2n),
// warp tile 32x64, mma.sync.m16n8k16 bf16.
#define STAGES 3
#define STAGE_BYTES 32768           // (128+128) rows * 128B
#define B_OFF 16384
#define GOOD_OFF (STAGES * STAGE_BYTES)
#define SMEM_DYN (GOOD_OFF + 512 + 1024)

__global__ void __launch_bounds__(256, 2) k_gemm() {
    extern __shared__ char smraw[];
    const uint32_t sb0 = smem_u32(smraw);
    const uint32_t sbase = (sb0 + 1023) & ~1023u;
    char* smc = smraw + (sbase - sb0);
    float* goodf = (float*)(smc + GOOD_OFF);

    const int tid = threadIdx.x;
    const int lid = tid & 31;
    const int w = tid >> 5;
    const int wm = w >> 1;          // 0..3
    const int wn = w & 1;           // 0..1
    const int n0 = blockIdx.x * 128;
    const int m0 = blockIdx.y * 128;

    if (tid < 128) goodf[tid] = (float)g_good[n0 + tid];

    // per-thread load geometry: idx = tid + it*256 -> row=idx>>3, ch=idx&7
    const int lrow = tid >> 3;      // 0..31
    const int lch = tid & 7;
    uint32_t soff[4];
    #pragma unroll
    for (int it = 0; it < 4; it++) {
        uint32_t o = (uint32_t)(lrow + it * 32) * 128 + lch * 16;
        soff[it] = SWZ(o);
    }

    float acc[2][8][4];
    #pragma unroll
    for (int i = 0; i < 2; i++)
        #pragma unroll
        for (int j = 0; j < 8; j++)
            #pragma unroll
            for (int k = 0; k < 4; k++) acc[i][j][k] = 0.0f;

    auto load_stage = [&](int s, int kc) {
        uint32_t sa = sbase + s * STAGE_BYTES;
        const __nv_bfloat16* gA = g_Abf + (size_t)(m0 + lrow) * DD + kc * 64 + lch * 8;
        const __nv_bfloat16* gB = g_Bbf + (size_t)(n0 + lrow) * DD + kc * 64 + lch * 8;
        #pragma unroll
        for (int it = 0; it < 4; it++) {
            cpa16(sa + soff[it], gA + (size_t)it * 32 * DD);
            cpa16(sa + B_OFF + soff[it], gB + (size_t)it * 32 * DD);
        }
        cpa_commit();
    };

    load_stage(0, 0);
    load_stage(1, 1);

    const int arow = wm * 32 + (lid & 15);
    const int acolh = lid >> 4;               // 0/1 -> +8 k elems
    const int brow = wn * 64 + ((lid >> 4) << 3) + (lid & 7);
    const int bcolh = (lid >> 3) & 1;

    for (int c = 0; c < 8; c++) {
        if (c < 7) asm volatile("cp.async.wait_group 1;" ::: "memory");
        else       asm volatile("cp.async.wait_group 0;" ::: "memory");
        __syncthreads();
        if (c + 2 < 8) load_stage((c + 2) % STAGES, c + 2);

        uint32_t sa = sbase + (c % STAGES) * STAGE_BYTES;
        uint32_t sb = sa + B_OFF;
        #pragma unroll
        for (int kk = 0; kk < 4; kk++) {
            uint32_t a[2][4];
            #pragma unroll
            for (int mi = 0; mi < 2; mi++) {
                uint32_t o = (uint32_t)(arow + mi * 16) * 128 +
                             (kk * 2 + acolh) * 16;
                ldsm4(a[mi], sa + SWZ(o));
            }
            uint32_t b[8][2];
            #pragma unroll
            for (int nj = 0; nj < 4; nj++) {
                uint32_t q[4];
                uint32_t o = (uint32_t)(brow + nj * 16) * 128 +
                             (kk * 2 + bcolh) * 16;
                ldsm4(q, sb + SWZ(o));
                b[2 * nj][0] = q[0]; b[2 * nj][1] = q[1];
                b[2 * nj + 1][0] = q[2]; b[2 * nj + 1][1] = q[3];
            }
            #pragma unroll
            for (int mi = 0; mi < 2; mi++)
                #pragma unroll
                for (int ni = 0; ni < 8; ni++)
                    mma16816(acc[mi][ni], a[mi], b[ni]);
        }
        __syncthreads();
    }

    // epilogue: masked exp row-sums
    float rs[4] = {0.0f, 0.0f, 0.0f, 0.0f};
    #pragma unroll
    for (int mi = 0; mi < 2; mi++) {
        #pragma unroll
        for (int ni = 0; ni < 8; ni++) {
            int col = wn * 64 + ni * 8 + ((lid & 3) << 1);
            float g0 = goodf[col], g1 = goodf[col + 1];
            float* cacc = acc[mi][ni];
            rs[mi * 2 + 0] += g0 * __expf(fmaf(OIM_SCALE, cacc[0], -OIM_SCALE))
                            + g1 * __expf(fmaf(OIM_SCALE, cacc[1], -OIM_SCALE));
            rs[mi * 2 + 1] += g0 * __expf(fmaf(OIM_SCALE, cacc[2], -OIM_SCALE))
                            + g1 * __expf(fmaf(OIM_SCALE, cacc[3], -OIM_SCALE));
        }
    }
    #pragma unroll
    for (int i = 0; i < 4; i++) {
        rs[i] += __shfl_xor_sync(0xffffffffu, rs[i], 1);
        rs[i] += __shfl_xor_sync(0xffffffffu, rs[i], 2);
    }
    if ((lid & 3) == 0) {
        int r0 = m0 + wm * 32 + (lid >> 2);
        atomicAdd(&g_rowsum[r0 +  0], rs[0]);
        atomicAdd(&g_rowsum[r0 +  8], rs[1]);
        atomicAdd(&g_rowsum[r0 + 16], rs[2]);
        atomicAdd(&g_rowsum[r0 + 24], rs[3]);
    }
}

// ---------------- 7: final reduce --------------------------------------------
__global__ void k_final(float* __restrict__ out) {
    int t = threadIdx.x;          // 1024
    float s = 0.0f;
    for (int b = t; b < BB; b += 1024)
        s += (OIM_SCALE + logf(g_rowsum[b])) - g_target[b];
    #pragma unroll
    for (int o = 16; o; o >>= 1) s += __shfl_xor_sync(0xffffffffu, s, o);
    __shared__ float sh[32];
    if ((t & 31) == 0) sh[t >> 5] = s;
    __syncthreads();
    if (t == 0) {
        float tot = 0.0f;
        #pragma unroll
        for (int w = 0; w < 32; w++) tot += sh[w];
        out[0] = tot / (float)BB;
    }
}

// ---------------- launch ------------------------------------------------------
extern "C" void kernel_launch(void* const* d_in, const int* in_sizes, int n_in,
                              void* d_out, int out_size) {
    const float* inputs   = (const float*)d_in[0];
    const int*   labels   = (const int*)  d_in[1];
    const float* emb_cq   = (const float*)d_in[2];
    const int*   label_cq = (const int*)  d_in[3];
    const int*   header   = (const int*)  d_in[5];
    float* out = (float*)d_out;

    cudaFuncSetAttribute(k_gemm, cudaFuncAttributeMaxDynamicSharedMemorySize,
                         SMEM_DYN);

    k_init<<<256, 256>>>();
    k_row<<<BB, 128>>>(inputs, labels);
    k_class<<<UU, 128>>>();
    k_rank<<<1, UU>>>();
    k_build<<<QQ, 128>>>(emb_cq, label_cq, header);
    k_target<<<BB, 128>>>(labels);
    dim3 grid(QQ / 128, BB / 128);
    k_gemm<<<grid, 256, SMEM_DYN>>>();
    k_final<<<1, 1024>>>(out);
}